// round 1
// baseline (speedup 1.0000x reference)
#include <cuda_runtime.h>

// MDN_module: B x (2 -> 64 -> 4 MLP, Lyapunov-stabilized diag-Gaussian rsample + logprob sum)
// Inputs (metadata order): x[B,2] y[B,1,2] eps[B,1,2] W1[2,64] b1[64] W2[64,4] b2[4] Wv[2,2]
// Output: fx[B,1,2] flattened (2B floats) followed by logp_y scalar at out[2B].

typedef unsigned long long u64;

#define HID 64
#define PAIRS 4          // row-pairs per thread per group (8 rows)
#define NTHREADS 256

__device__ double g_sum;   // sum over rows of (d0^2/v0 + d1^2/v1 + f2 + f3)

// ---------------- f32x2 packed helpers (Blackwell FFMA2 path) ----------------
__device__ __forceinline__ u64 pk2(float lo, float hi) {
    u64 r; asm("mov.b64 %0, {%1, %2};" : "=l"(r) : "f"(lo), "f"(hi)); return r;
}
__device__ __forceinline__ void upk2(float& lo, float& hi, u64 v) {
    asm("mov.b64 {%0, %1}, %2;" : "=f"(lo), "=f"(hi) : "l"(v));
}
__device__ __forceinline__ u64 ffma2(u64 a, u64 b, u64 c) {
    u64 d; asm("fma.rn.f32x2 %0, %1, %2, %3;" : "=l"(d) : "l"(a), "l"(b), "l"(c)); return d;
}

// ---------------- per-row epilogue ----------------
// returns (d0^2/v0 + d1^2/v1 + f2 + f3); writes fx0, fx1
__device__ __forceinline__ float row_tail(
    float x0, float x1, float mu0, float mu1, float f2, float f3,
    float y0, float y1, float e0, float e1,
    float wv00, float wv01, float wv10, float wv11,
    float& fx0, float& fx1)
{
    // V(x) = ||x @ Wv||^2 + 1e-3   (z_c = x0*Wv[0,c] + x1*Wv[1,c])
    float z0 = fmaf(x0, wv00, x1 * wv10);
    float z1 = fmaf(x0, wv01, x1 * wv11);
    float Vx = fmaf(z0, z0, fmaf(z1, z1, 1e-3f));
    float m0 = fmaf(mu0, wv00, mu1 * wv10);
    float m1 = fmaf(mu0, wv01, mu1 * wv11);
    float Vmu = fmaf(m0, m0, fmaf(m1, m1, 1e-3f));
    // beta*Vx - relu(beta*Vx - Vmu) == min(beta*Vx, Vmu)  (exact in fp)
    float scale = fminf(0.99f * Vx, Vmu) / Vmu;
    float ms0 = mu0 * scale;
    float ms1 = mu1 * scale;
    float v0 = __expf(f2);
    float v1 = __expf(f3);
    float r0 = rsqrtf(v0);             // sqrt(v) = v*r ; 1/v = r*r
    float r1 = rsqrtf(v1);
    fx0 = fmaf(v0 * r0, e0, ms0);
    fx1 = fmaf(v1 * r1, e1, ms1);
    float d0 = y0 - ms0;
    float d1 = y1 - ms1;
    // log(v0)+log(v1) == f2+f3 exactly (v = exp(f))
    float s = fmaf(d0 * d0, r0 * r0, f2 + f3);
    s = fmaf(d1 * d1, r1 * r1, s);
    return s;
}

// ---------------- kernels ----------------
__global__ void zero_kernel() { g_sum = 0.0; }

__global__ void finalize_kernel(float* out, long long B) {
    // logp_y = 0.5 * sum + B * log(2*pi)
    out[2 * B] = (float)(0.5 * g_sum + (double)B * 1.8378770664093453);
}

__global__ void __launch_bounds__(NTHREADS)
mdn_kernel(const float4* __restrict__ x4, const float4* __restrict__ y4,
           const float4* __restrict__ e4,
           const float* __restrict__ W1, const float* __restrict__ b1,
           const float* __restrict__ W2, const float* __restrict__ b2,
           const float* __restrict__ Wv,
           float4* __restrict__ o4, int nGroups)
{
    __shared__ u64 sw0[HID], sw1[HID], sbb[HID];
    __shared__ u64 sw2[4][HID];
    __shared__ float wsum[NTHREADS / 32];

    int t = threadIdx.x;
    if (t < HID) {
        float w0 = W1[t], w1 = W1[HID + t], b = b1[t];
        sw0[t] = pk2(w0, w0);
        sw1[t] = pk2(w1, w1);
        sbb[t] = pk2(b, b);
#pragma unroll
        for (int k = 0; k < 4; k++) {
            float w = W2[t * 4 + k];
            sw2[k][t] = pk2(w, w);
        }
    }
    __syncthreads();

    float wv00 = Wv[0], wv01 = Wv[1], wv10 = Wv[2], wv11 = Wv[3];
    u64 pb2[4];
#pragma unroll
    for (int k = 0; k < 4; k++) pb2[k] = pk2(b2[k], b2[k]);

    float lsum = 0.0f;
    int tid = blockIdx.x * blockDim.x + threadIdx.x;
    int stride = gridDim.x * blockDim.x;

    for (int g = tid; g < nGroups; g += stride) {
        int base = g * PAIRS;             // float4 index; pair p = rows (8g+2p, 8g+2p+1)
        u64 X0[PAIRS], X1[PAIRS], acc[PAIRS][4];
#pragma unroll
        for (int p = 0; p < PAIRS; p++) {
            float4 xv = x4[base + p];     // {x0_a, x1_a, x0_b, x1_b}
            X0[p] = pk2(xv.x, xv.z);
            X1[p] = pk2(xv.y, xv.w);
#pragma unroll
            for (int k = 0; k < 4; k++) acc[p][k] = pb2[k];
        }

#pragma unroll 4
        for (int j = 0; j < HID; j++) {
            u64 w0 = sw0[j], w1 = sw1[j], bb = sbb[j];
            u64 c0 = sw2[0][j], c1 = sw2[1][j], c2 = sw2[2][j], c3 = sw2[3][j];
#pragma unroll
            for (int p = 0; p < PAIRS; p++) {
                u64 pre = ffma2(X1[p], w1, bb);
                pre = ffma2(X0[p], w0, pre);
                float ha, hb;
                upk2(ha, hb, pre);
                ha = fmaxf(ha, 0.0f);     // FMNMX -> alu pipe, off the fma pipe
                hb = fmaxf(hb, 0.0f);
                u64 h = pk2(ha, hb);
                acc[p][0] = ffma2(h, c0, acc[p][0]);
                acc[p][1] = ffma2(h, c1, acc[p][1]);
                acc[p][2] = ffma2(h, c2, acc[p][2]);
                acc[p][3] = ffma2(h, c3, acc[p][3]);
            }
        }

#pragma unroll
        for (int p = 0; p < PAIRS; p++) {
            float f0a, f0b, f1a, f1b, f2a, f2b, f3a, f3b;
            upk2(f0a, f0b, acc[p][0]);
            upk2(f1a, f1b, acc[p][1]);
            upk2(f2a, f2b, acc[p][2]);
            upk2(f3a, f3b, acc[p][3]);
            float x0a, x0b, x1a, x1b;
            upk2(x0a, x0b, X0[p]);
            upk2(x1a, x1b, X1[p]);
            float4 yv = y4[base + p];
            float4 ev = e4[base + p];
            float fa0, fa1, fb0, fb1;
            lsum += row_tail(x0a, x1a, f0a, f1a, f2a, f3a, yv.x, yv.y, ev.x, ev.y,
                             wv00, wv01, wv10, wv11, fa0, fa1);
            lsum += row_tail(x0b, x1b, f0b, f1b, f2b, f3b, yv.z, yv.w, ev.z, ev.w,
                             wv00, wv01, wv10, wv11, fb0, fb1);
            float4 o;
            o.x = fa0; o.y = fa1; o.z = fb0; o.w = fb1;
            o4[base + p] = o;
        }
    }

    // block reduction -> one double atomic per block
#pragma unroll
    for (int off = 16; off; off >>= 1)
        lsum += __shfl_xor_sync(0xffffffffu, lsum, off);
    if ((threadIdx.x & 31) == 0) wsum[threadIdx.x >> 5] = lsum;
    __syncthreads();
    if (threadIdx.x < NTHREADS / 32) {
        float v = wsum[threadIdx.x];
#pragma unroll
        for (int off = (NTHREADS / 64); off; off >>= 1)
            v += __shfl_xor_sync((1u << (NTHREADS / 32)) - 1u, v, off);
        if (threadIdx.x == 0) atomicAdd(&g_sum, (double)v);
    }
}

// scalar fallback for rows not covered by the 8-row groups
__global__ void tail_kernel(const float* __restrict__ x, const float* __restrict__ y,
                            const float* __restrict__ e,
                            const float* __restrict__ W1, const float* __restrict__ b1,
                            const float* __restrict__ W2, const float* __restrict__ b2,
                            const float* __restrict__ Wv,
                            float* __restrict__ out, int start, int B)
{
    int r = start + blockIdx.x * blockDim.x + threadIdx.x;
    if (r >= B) return;
    float x0 = x[2 * r], x1 = x[2 * r + 1];
    float f[4] = { b2[0], b2[1], b2[2], b2[3] };
    for (int j = 0; j < HID; j++) {
        float h = fmaxf(fmaf(x0, W1[j], fmaf(x1, W1[HID + j], b1[j])), 0.0f);
#pragma unroll
        for (int k = 0; k < 4; k++) f[k] = fmaf(h, W2[j * 4 + k], f[k]);
    }
    float fx0, fx1;
    float s = row_tail(x0, x1, f[0], f[1], f[2], f[3],
                       y[2 * r], y[2 * r + 1], e[2 * r], e[2 * r + 1],
                       Wv[0], Wv[1], Wv[2], Wv[3], fx0, fx1);
    out[2 * r] = fx0;
    out[2 * r + 1] = fx1;
    atomicAdd(&g_sum, (double)s);
}

extern "C" void kernel_launch(void* const* d_in, const int* in_sizes, int n_in,
                              void* d_out, int out_size)
{
    const float* x  = (const float*)d_in[0];
    const float* y  = (const float*)d_in[1];
    const float* e  = (const float*)d_in[2];
    const float* W1 = (const float*)d_in[3];
    const float* b1 = (const float*)d_in[4];
    const float* W2 = (const float*)d_in[5];
    const float* b2 = (const float*)d_in[6];
    const float* Wv = (const float*)d_in[7];
    float* out = (float*)d_out;

    long long B = (long long)in_sizes[0] / 2;
    int nGroups = (int)(B / 8);

    zero_kernel<<<1, 1>>>();
    if (nGroups > 0) {
        int blocks = (nGroups + NTHREADS - 1) / NTHREADS;
        mdn_kernel<<<blocks, NTHREADS>>>((const float4*)x, (const float4*)y,
                                         (const float4*)e, W1, b1, W2, b2, Wv,
                                         (float4*)out, nGroups);
    }
    long long startRow = (long long)nGroups * 8;
    if (startRow < B) {
        int rem = (int)(B - startRow);
        tail_kernel<<<(rem + 127) / 128, 128>>>(x, y, e, W1, b1, W2, b2, Wv,
                                                out, (int)startRow, (int)B);
    }
    finalize_kernel<<<1, 1>>>(out, B);
}